// round 11
// baseline (speedup 1.0000x reference)
#include <cuda_runtime.h>
#include <cstdint>

#define N_MOLS  32768
#define N_ATOMS 4194304
#define THREADS 512
// 4 atoms per thread
#define N_THREADS_TOTAL (N_ATOMS / 4)
#define N_BLOCKS (N_THREADS_TOTAL / THREADS)   // 2048

__global__ void zero_energy_kernel(float4* __restrict__ energy4) {
    int i = blockIdx.x * blockDim.x + threadIdx.x;   // N_MOLS/4 = 8192 threads
    energy4[i] = make_float4(0.f, 0.f, 0.f, 0.f);
    cudaTriggerProgrammaticLaunchCompletion();
}

__device__ __forceinline__ float tanh_approx(float x) {
    float y;
    asm("tanh.approx.f32 %0, %1;" : "=f"(y) : "f"(x));
    return y;
}

__device__ __forceinline__ uint64_t mkpolicy_evict_last() {
    uint64_t p;
    asm("createpolicy.fractional.L2::evict_last.b64 %0, 1.0;" : "=l"(p));
    return p;
}
__device__ __forceinline__ uint64_t mkpolicy_evict_first() {
    uint64_t p;
    asm("createpolicy.fractional.L2::evict_first.b64 %0, 1.0;" : "=l"(p));
    return p;
}

__device__ __forceinline__ float4 ldg_el_f4(const float4* p, uint64_t pol) {
    float4 v;
    asm volatile("ld.global.L2::cache_hint.v4.f32 {%0,%1,%2,%3}, [%4], %5;"
                 : "=f"(v.x), "=f"(v.y), "=f"(v.z), "=f"(v.w) : "l"(p), "l"(pol));
    return v;
}
__device__ __forceinline__ int4 ldg_el_i4(const int4* p, uint64_t pol) {
    int4 v;
    asm volatile("ld.global.L2::cache_hint.v4.s32 {%0,%1,%2,%3}, [%4], %5;"
                 : "=r"(v.x), "=r"(v.y), "=r"(v.z), "=r"(v.w) : "l"(p), "l"(pol));
    return v;
}
__device__ __forceinline__ void stg_ef_f4(float4* p, float4 v, uint64_t pol) {
    asm volatile("st.global.L2::cache_hint.v4.f32 [%0], {%1,%2,%3,%4}, %5;"
                 :: "l"(p), "f"(v.x), "f"(v.y), "f"(v.z), "f"(v.w), "l"(pol) : "memory");
}

__global__ __launch_bounds__(THREADS) void sumpool_kernel(
    const float4* __restrict__ xyz4,     // N_ATOMS*3 floats viewed as float4
    const int4*   __restrict__ ids4,     // N_ATOMS ints viewed as int4
    const float*  __restrict__ w,        // 3 floats
    float*        __restrict__ energy,   // N_MOLS
    float4*       __restrict__ grad4)    // N_ATOMS*3 floats viewed as float4
{
    const int tid  = blockIdx.x * blockDim.x + threadIdx.x;
    const int lane = threadIdx.x & 31;

    const uint64_t pol_keep = mkpolicy_evict_last();
    const uint64_t pol_pass = mkpolicy_evict_first();

    const float w0 = __ldg(w + 0);
    const float w1 = __ldg(w + 1);
    const float w2 = __ldg(w + 2);

    // 4 atoms = 3 coalesced float4 loads + 1 int4 (front-batched, MLP=4)
    const float4 a = ldg_el_f4(&xyz4[tid * 3 + 0], pol_keep);
    const float4 b = ldg_el_f4(&xyz4[tid * 3 + 1], pol_keep);
    const float4 c = ldg_el_f4(&xyz4[tid * 3 + 2], pol_keep);
    const int4  id = ldg_el_i4(&ids4[tid],         pol_keep);

    // atom k coords: atom0: a.x a.y a.z | atom1: a.w b.x b.y
    //                atom2: b.z b.w c.x | atom3: c.y c.z c.w
    const float t0 = tanh_approx(a.x * w0 + a.y * w1 + a.z * w2);
    const float t1 = tanh_approx(a.w * w0 + b.x * w1 + b.y * w2);
    const float t2 = tanh_approx(b.z * w0 + b.w * w1 + c.x * w2);
    const float t3 = tanh_approx(c.y * w0 + c.z * w1 + c.w * w2);

    const float g0 = 1.0f - t0 * t0;
    const float g1 = 1.0f - t1 * t1;
    const float g2 = 1.0f - t2 * t2;
    const float g3 = 1.0f - t3 * t3;

    stg_ef_f4(&grad4[tid * 3 + 0], make_float4(g0 * w0, g0 * w1, g0 * w2, g1 * w0), pol_pass);
    stg_ef_f4(&grad4[tid * 3 + 1], make_float4(g1 * w1, g1 * w2, g2 * w0, g2 * w1), pol_pass);
    stg_ef_f4(&grad4[tid * 3 + 2], make_float4(g2 * w2, g3 * w0, g3 * w1, g3 * w2), pol_pass);

    // Wait for zero kernel's writes to energy[] (everything above is independent).
    cudaGridDependencySynchronize();

    // ---- segment sum of t0..t3 over sorted ids ----
    int   cur = id.x;
    float s   = t0;
    if (id.y == cur) { s += t1; } else { atomicAdd(&energy[cur], s); cur = id.y; s = t1; }
    if (id.z == cur) { s += t2; } else { atomicAdd(&energy[cur], s); cur = id.z; s = t2; }
    if (id.w == cur) { s += t3; } else { atomicAdd(&energy[cur], s); cur = id.w; s = t3; }

    // warp-level segmented reduction (ids sorted => equal-id lanes contiguous)
    #pragma unroll
    for (int off = 1; off < 32; off <<= 1) {
        const float v   = __shfl_down_sync(0xffffffffu, s,   off);
        const int   oid = __shfl_down_sync(0xffffffffu, cur, off);
        if (lane + off < 32 && oid == cur) s += v;
    }
    const int prev = __shfl_up_sync(0xffffffffu, cur, 1);
    if (lane == 0 || prev != cur) {
        atomicAdd(&energy[cur], s);   // run leader flushes whole-run tail sum
    }
}

extern "C" void kernel_launch(void* const* d_in, const int* in_sizes, int n_in,
                              void* d_out, int out_size) {
    const float4* xyz4 = (const float4*)d_in[0];
    const int4*   ids4 = (const int4*)d_in[1];
    const float*  w    = (const float*)d_in[2];

    float* energy = (float*)d_out;                      // [N_MOLS]
    float4* grad4 = (float4*)((float*)d_out + N_MOLS);  // [N_ATOMS*3] floats

    zero_energy_kernel<<<(N_MOLS / 4) / 256, 256>>>((float4*)energy);

    // PDL: main kernel prologue overlaps the zero kernel + launch latency.
    cudaLaunchConfig_t cfg = {};
    cfg.gridDim  = dim3(N_BLOCKS, 1, 1);
    cfg.blockDim = dim3(THREADS, 1, 1);
    cudaLaunchAttribute attrs[1];
    attrs[0].id = cudaLaunchAttributeProgrammaticStreamSerialization;
    attrs[0].val.programmaticStreamSerializationAllowed = 1;
    cfg.attrs    = attrs;
    cfg.numAttrs = 1;
    cudaLaunchKernelEx(&cfg, sumpool_kernel, xyz4, ids4, w, energy, grad4);
}

// round 12
// speedup vs baseline: 1.0168x; 1.0168x over previous
#include <cuda_runtime.h>
#include <cstdint>

#define N_MOLS  32768
#define N_ATOMS 4194304
#define THREADS 256
// 4 atoms per thread
#define N_THREADS_TOTAL (N_ATOMS / 4)
#define N_BLOCKS (N_THREADS_TOTAL / THREADS)

// Zero-invariant scratch accumulator: zero-initialized at module load; the
// epilogue kernel restores it to zero every launch, so kernel_launch always
// sees it zeroed on entry. Lets the main kernel start with no prologue.
__device__ float g_scratch[N_MOLS];

__device__ __forceinline__ float tanh_approx(float x) {
    float y;
    asm("tanh.approx.f32 %0, %1;" : "=f"(y) : "f"(x));
    return y;
}

__device__ __forceinline__ uint64_t mkpolicy_evict_last() {
    uint64_t p;
    asm("createpolicy.fractional.L2::evict_last.b64 %0, 1.0;" : "=l"(p));
    return p;
}
__device__ __forceinline__ uint64_t mkpolicy_evict_first() {
    uint64_t p;
    asm("createpolicy.fractional.L2::evict_first.b64 %0, 1.0;" : "=l"(p));
    return p;
}

__device__ __forceinline__ float4 ldg_el_f4(const float4* p, uint64_t pol) {
    float4 v;
    asm volatile("ld.global.L2::cache_hint.v4.f32 {%0,%1,%2,%3}, [%4], %5;"
                 : "=f"(v.x), "=f"(v.y), "=f"(v.z), "=f"(v.w) : "l"(p), "l"(pol));
    return v;
}
__device__ __forceinline__ int4 ldg_el_i4(const int4* p, uint64_t pol) {
    int4 v;
    asm volatile("ld.global.L2::cache_hint.v4.s32 {%0,%1,%2,%3}, [%4], %5;"
                 : "=r"(v.x), "=r"(v.y), "=r"(v.z), "=r"(v.w) : "l"(p), "l"(pol));
    return v;
}
__device__ __forceinline__ void stg_ef_f4(float4* p, float4 v, uint64_t pol) {
    asm volatile("st.global.L2::cache_hint.v4.f32 [%0], {%1,%2,%3,%4}, %5;"
                 :: "l"(p), "f"(v.x), "f"(v.y), "f"(v.z), "f"(v.w), "l"(pol) : "memory");
}

__global__ __launch_bounds__(THREADS) void sumpool_kernel(
    const float4* __restrict__ xyz4,     // N_ATOMS*3 floats viewed as float4
    const int4*   __restrict__ ids4,     // N_ATOMS ints viewed as int4
    const float*  __restrict__ w,        // 3 floats
    float4*       __restrict__ grad4)    // N_ATOMS*3 floats viewed as float4
{
    const int tid  = blockIdx.x * blockDim.x + threadIdx.x;
    const int lane = threadIdx.x & 31;

    const uint64_t pol_keep = mkpolicy_evict_last();
    const uint64_t pol_pass = mkpolicy_evict_first();

    const float w0 = __ldg(w + 0);
    const float w1 = __ldg(w + 1);
    const float w2 = __ldg(w + 2);

    // 4 atoms = 3 coalesced float4 loads + 1 int4 (front-batched, MLP=4)
    const float4 a = ldg_el_f4(&xyz4[tid * 3 + 0], pol_keep);
    const float4 b = ldg_el_f4(&xyz4[tid * 3 + 1], pol_keep);
    const float4 c = ldg_el_f4(&xyz4[tid * 3 + 2], pol_keep);
    const int4  id = ldg_el_i4(&ids4[tid],         pol_keep);

    // atom k coords: atom0: a.x a.y a.z | atom1: a.w b.x b.y
    //                atom2: b.z b.w c.x | atom3: c.y c.z c.w
    const float t0 = tanh_approx(a.x * w0 + a.y * w1 + a.z * w2);
    const float t1 = tanh_approx(a.w * w0 + b.x * w1 + b.y * w2);
    const float t2 = tanh_approx(b.z * w0 + b.w * w1 + c.x * w2);
    const float t3 = tanh_approx(c.y * w0 + c.z * w1 + c.w * w2);

    const float g0 = 1.0f - t0 * t0;
    const float g1 = 1.0f - t1 * t1;
    const float g2 = 1.0f - t2 * t2;
    const float g3 = 1.0f - t3 * t3;

    stg_ef_f4(&grad4[tid * 3 + 0], make_float4(g0 * w0, g0 * w1, g0 * w2, g1 * w0), pol_pass);
    stg_ef_f4(&grad4[tid * 3 + 1], make_float4(g1 * w1, g1 * w2, g2 * w0, g2 * w1), pol_pass);
    stg_ef_f4(&grad4[tid * 3 + 2], make_float4(g2 * w2, g3 * w0, g3 * w1, g3 * w2), pol_pass);

    // ---- segment sum of t0..t3 over sorted ids, into zero-invariant scratch ----
    int   cur = id.x;
    float s   = t0;
    if (id.y == cur) { s += t1; } else { atomicAdd(&g_scratch[cur], s); cur = id.y; s = t1; }
    if (id.z == cur) { s += t2; } else { atomicAdd(&g_scratch[cur], s); cur = id.z; s = t2; }
    if (id.w == cur) { s += t3; } else { atomicAdd(&g_scratch[cur], s); cur = id.w; s = t3; }

    // warp-level segmented reduction (ids sorted => equal-id lanes contiguous)
    #pragma unroll
    for (int off = 1; off < 32; off <<= 1) {
        const float v   = __shfl_down_sync(0xffffffffu, s,   off);
        const int   oid = __shfl_down_sync(0xffffffffu, cur, off);
        if (lane + off < 32 && oid == cur) s += v;
    }
    const int prev = __shfl_up_sync(0xffffffffu, cur, 1);
    if (lane == 0 || prev != cur) {
        atomicAdd(&g_scratch[cur], s);   // run leader flushes whole-run tail sum
    }
}

// Epilogue: publish scratch -> energy, restore scratch invariant (zero).
__global__ void publish_energy_kernel(float4* __restrict__ energy4) {
    const int i = blockIdx.x * blockDim.x + threadIdx.x;   // 8192 threads
    cudaGridDependencySynchronize();   // wait for main kernel's atomics
    float4* s4 = reinterpret_cast<float4*>(g_scratch);
    energy4[i] = s4[i];
    s4[i] = make_float4(0.f, 0.f, 0.f, 0.f);
}

extern "C" void kernel_launch(void* const* d_in, const int* in_sizes, int n_in,
                              void* d_out, int out_size) {
    const float4* xyz4 = (const float4*)d_in[0];
    const int4*   ids4 = (const int4*)d_in[1];
    const float*  w    = (const float*)d_in[2];

    float* energy = (float*)d_out;                      // [N_MOLS]
    float4* grad4 = (float4*)((float*)d_out + N_MOLS);  // [N_ATOMS*3] floats

    // Main kernel: no prologue, starts immediately.
    sumpool_kernel<<<N_BLOCKS, THREADS>>>(xyz4, ids4, w, grad4);

    // Epilogue with PDL: its launch overlaps the main kernel's tail wave;
    // gridDependencySynchronize inside orders it after main's completion.
    cudaLaunchConfig_t cfg = {};
    cfg.gridDim  = dim3((N_MOLS / 4) / 256, 1, 1);   // 32 blocks
    cfg.blockDim = dim3(256, 1, 1);
    cudaLaunchAttribute attrs[1];
    attrs[0].id = cudaLaunchAttributeProgrammaticStreamSerialization;
    attrs[0].val.programmaticStreamSerializationAllowed = 1;
    cfg.attrs    = attrs;
    cfg.numAttrs = 1;
    cudaLaunchKernelEx(&cfg, publish_energy_kernel, (float4*)energy);
}